// round 15
// baseline (speedup 1.0000x reference)
#include <cuda_runtime.h>
#include <cuda_bf16.h>
#include <cstdint>

// ===========================================================================
// ChannelAttentionModule (DANet), B=32, C=512, N=H*W=1024, fp32.
//   S = feat @ feat^T ; W = softmax(rowmax(S)-S) = exp(rowmin-S)/sum ;
//   out = beta * (W @ feat) + x
// R15: (a) hoist all ldsm smem offsets out of the mainloops (fixes R14's
// 14% ALU regression on the trans-B path); (b) rotate the pipeline so the
// first MMA group's fragments for chunk c+1 are ldsm'd at the END of iter c
// (after CPW(2)+sync proves residency) — each barrier is followed
// immediately by MMAs, not by a serial ldsm stall. Zero extra registers.
// ===========================================================================

#define BDIM 32
#define CDIM 512
#define NDIM 1024
#define TSZ   2048                 // shorts per 128x16 A tile
#define BTSZ2 1024                 // shorts per 64x16  B tile (gram)
#define BTTSZ 1024                 // shorts per 16x64  B tile (av, trans)

// ---------------- scratch (static device globals: allowed) ----------------
__device__ float          g_scores[(size_t)BDIM * CDIM * CDIM];
__device__ __align__(16) unsigned short g_h [(size_t)BDIM * CDIM * NDIM]; // x hi  [b][c][n]
__device__ __align__(16) unsigned short g_l [(size_t)BDIM * CDIM * NDIM]; // x lo
__device__ __align__(16) unsigned short g_wh[(size_t)BDIM * CDIM * CDIM]; // W hi  [b][c][d]
__device__ __align__(16) unsigned short g_wl[(size_t)BDIM * CDIM * CDIM]; // W lo

// ---------------- helpers ---------------------------------------------------
__device__ __forceinline__ uint32_t smem_u32(const void* p) {
    uint32_t a;
    asm("{ .reg .u64 t; cvta.to.shared.u64 t, %1; cvt.u32.u64 %0, t; }"
        : "=r"(a) : "l"(p));
    return a;
}
__device__ __forceinline__ void ldsm4(uint32_t r[4], uint32_t addr) {
    asm volatile("ldmatrix.sync.aligned.m8n8.x4.shared.b16 {%0,%1,%2,%3}, [%4];"
                 : "=r"(r[0]), "=r"(r[1]), "=r"(r[2]), "=r"(r[3]) : "r"(addr));
}
__device__ __forceinline__ void ldsm4t(uint32_t r[4], uint32_t addr) {
    asm volatile("ldmatrix.sync.aligned.m8n8.x4.trans.shared.b16 {%0,%1,%2,%3}, [%4];"
                 : "=r"(r[0]), "=r"(r[1]), "=r"(r[2]), "=r"(r[3]) : "r"(addr));
}
__device__ __forceinline__ void mma16816(float d[4], const uint32_t a[4],
                                         const uint32_t b[2]) {
    asm volatile(
        "mma.sync.aligned.m16n8k16.row.col.f32.bf16.bf16.f32 "
        "{%0,%1,%2,%3}, {%4,%5,%6,%7}, {%8,%9}, {%0,%1,%2,%3};"
        : "+f"(d[0]), "+f"(d[1]), "+f"(d[2]), "+f"(d[3])
        : "r"(a[0]), "r"(a[1]), "r"(a[2]), "r"(a[3]), "r"(b[0]), "r"(b[1]));
}
__device__ __forceinline__ void cpa(uint32_t s, const void* g) {
    asm volatile("cp.async.cg.shared.global [%0], [%1], 16;" :: "r"(s), "l"(g));
}
#define CPC()  asm volatile("cp.async.commit_group;" ::: "memory")
#define CPW(n) asm volatile("cp.async.wait_group %0;" :: "n"(n) : "memory")

// K-major tile swizzle: row stride 32B, 16B halves swap every 4 rows.
__device__ __forceinline__ uint32_t tswz(int row, int kh) {
    return (uint32_t)(row * 32 + ((kh ^ ((row >> 2) & 1)) << 4));
}
// Trans-B tile swizzle: 128B rows, 16B block xor'd by row (low 3 bits).
__device__ __forceinline__ uint32_t bswz(int row, int c16) {
    return (uint32_t)(row * 128 + ((c16 ^ (row & 7)) << 4));
}

__device__ __forceinline__ void bsplit(float v, unsigned short& h, unsigned short& l) {
    __nv_bfloat16 hh = __float2bfloat16_rn(v);
    float r = v - __bfloat162float(hh);
    __nv_bfloat16 ll = __float2bfloat16_rn(r);
    h = *reinterpret_cast<unsigned short*>(&hh);
    l = *reinterpret_cast<unsigned short*>(&ll);
}

// ===========================================================================
// gram mainloop: fused 3-term 128(M) x 64(N), 4-stage, rotated pipeline.
// 8 warps as 4M x 2N, warp tile 32x32. Per chunk: 8 ldsm, 24 MMAs.
// ===========================================================================
template <int LD, int NC>
__device__ __forceinline__ void gemm64(
    const unsigned short* __restrict__ Ah, const unsigned short* __restrict__ Al,
    const unsigned short* __restrict__ Bh, const unsigned short* __restrict__ Bl,
    unsigned short (*SA)[2][TSZ],           // [4][2][TSZ]
    unsigned short (*SB)[2][BTSZ2],         // [4][2][BTSZ2]
    float acc[2][4][4])
{
    const int t = threadIdx.x, lane = t & 31, wid = t >> 5;

    const unsigned short* srcA[2] = { Ah, Al };
    const unsigned short* srcB[2] = { Bh, Bl };

    const int crow = t >> 1, ckh = t & 1;                 // A rows 0..127
    const size_t gA = (size_t)crow * LD + ckh * 8;
    const uint32_t sA = tswz(crow, ckh);
    const int bsel = t >> 7;                              // 0: Bh, 1: Bl
    const int bt = t & 127;
    const int brow = bt >> 1, bkh = bt & 1;               // B rows 0..63
    const size_t gB = (size_t)brow * LD + bkh * 8;
    const uint32_t sB = tswz(brow, bkh);

    const int wm = (wid & 3) * 32, wn = (wid >> 2) * 32;
    const int a_r = wm + (lane & 15), a_kh = lane >> 4;
    const int b_r = wn + (lane & 7) + ((lane >> 4) << 3), b_kh = (lane >> 3) & 1;

    // hoisted tile-local ldsm offsets
    uint32_t offA[2], offB[2];
#pragma unroll
    for (int mi = 0; mi < 2; mi++) offA[mi] = tswz(a_r + 16 * mi, a_kh);
#pragma unroll
    for (int nj = 0; nj < 2; nj++) offB[nj] = tswz(b_r + 16 * nj, b_kh);

#pragma unroll
    for (int pc = 0; pc < 3; pc++) {
        cpa(smem_u32(&SA[pc][0][0]) + sA, srcA[0] + gA + pc * 16);
        cpa(smem_u32(&SA[pc][1][0]) + sA, srcA[1] + gA + pc * 16);
        cpa(smem_u32(&SB[pc][bsel][0]) + sB, srcB[bsel] + gB + pc * 16);
        CPC();
    }
    CPW(2);
    __syncthreads();

    uint32_t AhF[2][4], AlF[2][4], BhF[2][4], BlF[2][4];
#pragma unroll
    for (int mi = 0; mi < 2; mi++) ldsm4(AhF[mi], smem_u32(&SA[0][0][0]) + offA[mi]);
#pragma unroll
    for (int nj = 0; nj < 2; nj++) ldsm4(BhF[nj], smem_u32(&SB[0][0][0]) + offB[nj]);

    for (int c = 0; c < NC; c++) {
        if (c + 3 < NC) {
            const int nb = (c + 3) & 3;
            const size_t go = (size_t)(c + 3) * 16;
            cpa(smem_u32(&SA[nb][0][0]) + sA, srcA[0] + gA + go);
            cpa(smem_u32(&SA[nb][1][0]) + sA, srcA[1] + gA + go);
            cpa(smem_u32(&SB[nb][bsel][0]) + sB, srcB[bsel] + gB + go);
        }
        CPC();

        const int cb = c & 3;
        const uint32_t bAl = smem_u32(&SA[cb][1][0]);
        const uint32_t bBl = smem_u32(&SB[cb][1][0]);

        // g1: Ah x Bh (fragments prefetched last iteration)
#pragma unroll
        for (int mi = 0; mi < 2; mi++)
#pragma unroll
            for (int ni = 0; ni < 4; ni++)
                mma16816(acc[mi][ni], AhF[mi], &BhF[ni >> 1][(ni & 1) * 2]);
        // g2: Ah x Bl
#pragma unroll
        for (int nj = 0; nj < 2; nj++) ldsm4(BlF[nj], bBl + offB[nj]);
#pragma unroll
        for (int mi = 0; mi < 2; mi++)
#pragma unroll
            for (int ni = 0; ni < 4; ni++)
                mma16816(acc[mi][ni], AhF[mi], &BlF[ni >> 1][(ni & 1) * 2]);
        // g3: Al x Bh
#pragma unroll
        for (int mi = 0; mi < 2; mi++) ldsm4(AlF[mi], bAl + offA[mi]);
#pragma unroll
        for (int mi = 0; mi < 2; mi++)
#pragma unroll
            for (int ni = 0; ni < 4; ni++)
                mma16816(acc[mi][ni], AlF[mi], &BhF[ni >> 1][(ni & 1) * 2]);

        CPW(2);
        __syncthreads();
        if (c + 1 < NC) {
            const int nb = (c + 1) & 3;
            const uint32_t bAh = smem_u32(&SA[nb][0][0]);
            const uint32_t bBh = smem_u32(&SB[nb][0][0]);
#pragma unroll
            for (int mi = 0; mi < 2; mi++) ldsm4(AhF[mi], bAh + offA[mi]);
#pragma unroll
            for (int nj = 0; nj < 2; nj++) ldsm4(BhF[nj], bBh + offB[nj]);
        }
    }
}

// ===========================================================================
// Stage 0: elementwise split x -> g_h / g_l  ([b][c][n])
// ===========================================================================
__global__ void prep_kernel(const float* __restrict__ x) {
    const size_t i = ((size_t)blockIdx.x * 256 + threadIdx.x) * 4;
    float4 v = *(const float4*)(x + i);
    unsigned short h[4], l[4];
    bsplit(v.x, h[0], l[0]); bsplit(v.y, h[1], l[1]);
    bsplit(v.z, h[2], l[2]); bsplit(v.w, h[3], l[3]);
    uint2 ph, pl;
    ph.x = h[0] | ((uint32_t)h[1] << 16); ph.y = h[2] | ((uint32_t)h[3] << 16);
    pl.x = l[0] | ((uint32_t)l[1] << 16); pl.y = l[2] | ((uint32_t)l[3] << 16);
    *(uint2*)(g_h + i) = ph;
    *(uint2*)(g_l + i) = pl;
}

// ===========================================================================
// Stage 1: Gram S = F F^T.  128x64 tiles, 20 upper-tri pairs/batch, mirrored.
// ===========================================================================
__global__ __launch_bounds__(256, 2)
void gram_mma() {
    __shared__ unsigned short SA[4][2][TSZ];     // 32 KB (Ah, Al)
    __shared__ unsigned short SB[4][2][BTSZ2];   // 16 KB (Bh, Bl)

    const int b = blockIdx.y;
    int p = blockIdx.x;                          // 0..19
    int ti = 0;
    while (p >= 8 - 2 * ti) { p -= 8 - 2 * ti; ti++; }
    const int tjn = 2 * ti + p;                  // 64-col block, tjn*64 >= ti*128

    float acc[2][4][4];
#pragma unroll
    for (int i = 0; i < 2; i++)
#pragma unroll
        for (int j = 0; j < 4; j++)
#pragma unroll
            for (int k = 0; k < 4; k++) acc[i][j][k] = 0.f;

    gemm64<NDIM, NDIM / 16>(
        g_h + (size_t)(b * CDIM + ti * 128) * NDIM,
        g_l + (size_t)(b * CDIM + ti * 128) * NDIM,
        g_h + (size_t)(b * CDIM + tjn * 64) * NDIM,
        g_l + (size_t)(b * CDIM + tjn * 64) * NDIM,
        SA, SB, acc);

    const int lane = threadIdx.x & 31, wid = threadIdx.x >> 5;
    const int wm = (wid & 3) * 32, wn = (wid >> 2) * 32;
    float* Cb = g_scores + (size_t)b * CDIM * CDIM;
    const int r0 = ti * 128 + wm + (lane >> 2);
    const int c0 = tjn * 64 + wn + 2 * (lane & 3);
#pragma unroll
    for (int mi = 0; mi < 2; mi++)
#pragma unroll
        for (int ni = 0; ni < 4; ni++) {
            const float* d = acc[mi][ni];
            const int gr = r0 + 16 * mi, gc = c0 + 8 * ni;
            *(float2*)&Cb[(size_t)gr * CDIM + gc]       = make_float2(d[0], d[1]);
            *(float2*)&Cb[(size_t)(gr + 8) * CDIM + gc] = make_float2(d[2], d[3]);
            Cb[(size_t)gc * CDIM + gr]           = d[0];
            Cb[(size_t)(gc + 1) * CDIM + gr]     = d[1];
            Cb[(size_t)gc * CDIM + gr + 8]       = d[2];
            Cb[(size_t)(gc + 1) * CDIM + gr + 8] = d[3];
        }
}

// ===========================================================================
// Stage 2: softmin rows of S -> bf16 hi/lo weights.
// ===========================================================================
__global__ void softmin_kernel() {
    const int b = blockIdx.y, r = blockIdx.x;
    const float* row = g_scores + ((size_t)b * CDIM + r) * CDIM;
    const int t = threadIdx.x;
    const int warp = t >> 5, lane = t & 31;

    float4 v = ((const float4*)row)[t];
    float mn = fminf(fminf(v.x, v.y), fminf(v.z, v.w));
#pragma unroll
    for (int o = 16; o > 0; o >>= 1)
        mn = fminf(mn, __shfl_xor_sync(0xffffffffu, mn, o));

    __shared__ float rmin[4], rsum[4];
    if (lane == 0) rmin[warp] = mn;
    __syncthreads();
    mn = fminf(fminf(rmin[0], rmin[1]), fminf(rmin[2], rmin[3]));

    float4 e;
    e.x = __expf(mn - v.x); e.y = __expf(mn - v.y);
    e.z = __expf(mn - v.z); e.w = __expf(mn - v.w);
    float s = e.x + e.y + e.z + e.w;
#pragma unroll
    for (int o = 16; o > 0; o >>= 1)
        s += __shfl_xor_sync(0xffffffffu, s, o);
    if (lane == 0) rsum[warp] = s;
    __syncthreads();
    s = rsum[0] + rsum[1] + rsum[2] + rsum[3];

    const float inv = __frcp_rn(s);
    unsigned short h[4], l[4];
    bsplit(e.x * inv, h[0], l[0]); bsplit(e.y * inv, h[1], l[1]);
    bsplit(e.z * inv, h[2], l[2]); bsplit(e.w * inv, h[3], l[3]);
    uint2 ph, pl;
    ph.x = h[0] | ((uint32_t)h[1] << 16); ph.y = h[2] | ((uint32_t)h[3] << 16);
    pl.x = l[0] | ((uint32_t)l[1] << 16); pl.y = l[2] | ((uint32_t)l[3] << 16);
    const size_t off = ((size_t)b * CDIM + r) * CDIM + t * 4;
    *(uint2*)(g_wh + off) = ph;
    *(uint2*)(g_wl + off) = pl;
}

// ===========================================================================
// Stage 3: out = beta * (W @ feat) + x.  128x64 tiles, 4-stage, rotated.
// A = W [c][d] K-major.  B = feat [d][n] via ldmatrix.trans (no copy).
// ===========================================================================
__global__ __launch_bounds__(256, 2)
void av_mma(const float* __restrict__ x, const float* __restrict__ beta,
            float* __restrict__ out) {
    __shared__ unsigned short SA[4][2][TSZ];     // 32 KB (Wh, Wl)
    __shared__ unsigned short SBt[4][2][BTTSZ];  // 16 KB (Fh, Fl, trans tiles)

    const int b = blockIdx.z, nblk = blockIdx.x, mblk = blockIdx.y;
    const int t = threadIdx.x, lane = t & 31, wid = t >> 5;

    const unsigned short* srcA[2] = {
        g_wh + (size_t)(b * CDIM + mblk * 128) * CDIM,
        g_wl + (size_t)(b * CDIM + mblk * 128) * CDIM };
    const unsigned short* srcB[2] = {
        g_h + (size_t)b * CDIM * NDIM + nblk * 64,
        g_l + (size_t)b * CDIM * NDIM + nblk * 64 };

    const int crow = t >> 1, ckh = t & 1;                 // A rows 0..127
    const size_t gA = (size_t)crow * CDIM + ckh * 8;
    const uint32_t sA = tswz(crow, ckh);
    const int bsel = t >> 7;                              // 0: Fh, 1: Fl
    const int bt = t & 127;
    const int brow = bt >> 3, bc16 = bt & 7;              // B rows 0..15 (d)
    const size_t gB = (size_t)brow * NDIM + bc16 * 8;
    const uint32_t sB = bswz(brow, bc16);

    const int wm = (wid & 3) * 32, wn = (wid >> 2) * 32;
    const int a_r = wm + (lane & 15), a_kh = lane >> 4;
    const int bk_r = (lane & 7) + (((lane >> 3) & 1) << 3);
    const int bc_b = (wn >> 3) + (lane >> 4);

    // hoisted ldsm offsets
    uint32_t offA[2], offBt[2];
#pragma unroll
    for (int mi = 0; mi < 2; mi++) offA[mi] = tswz(a_r + 16 * mi, a_kh);
#pragma unroll
    for (int nj = 0; nj < 2; nj++) offBt[nj] = bswz(bk_r, bc_b + 2 * nj);

    float acc[2][4][4];
#pragma unroll
    for (int i = 0; i < 2; i++)
#pragma unroll
        for (int j = 0; j < 4; j++)
#pragma unroll
            for (int k = 0; k < 4; k++) acc[i][j][k] = 0.f;

    const int NC = CDIM / 16;                    // 32
#pragma unroll
    for (int pc = 0; pc < 3; pc++) {
        cpa(smem_u32(&SA[pc][0][0]) + sA, srcA[0] + gA + pc * 16);
        cpa(smem_u32(&SA[pc][1][0]) + sA, srcA[1] + gA + pc * 16);
        cpa(smem_u32(&SBt[pc][bsel][0]) + sB, srcB[bsel] + gB + (size_t)pc * 16 * NDIM);
        CPC();
    }
    CPW(2);
    __syncthreads();

    uint32_t AhF[2][4], AlF[2][4], BhF[2][4], BlF[2][4];
#pragma unroll
    for (int mi = 0; mi < 2; mi++) ldsm4(AhF[mi], smem_u32(&SA[0][0][0]) + offA[mi]);
#pragma unroll
    for (int nj = 0; nj < 2; nj++) ldsm4t(BhF[nj], smem_u32(&SBt[0][0][0]) + offBt[nj]);

    for (int c = 0; c < NC; c++) {
        if (c + 3 < NC) {
            const int nb = (c + 3) & 3;
            cpa(smem_u32(&SA[nb][0][0]) + sA, srcA[0] + gA + (size_t)(c + 3) * 16);
            cpa(smem_u32(&SA[nb][1][0]) + sA, srcA[1] + gA + (size_t)(c + 3) * 16);
            cpa(smem_u32(&SBt[nb][bsel][0]) + sB,
                srcB[bsel] + gB + (size_t)(c + 3) * 16 * NDIM);
        }
        CPC();

        const int cb = c & 3;
        const uint32_t bAl = smem_u32(&SA[cb][1][0]);
        const uint32_t bBl = smem_u32(&SBt[cb][1][0]);

        // g1: Wh x Fh (prefetched)
#pragma unroll
        for (int mi = 0; mi < 2; mi++)
#pragma unroll
            for (int ni = 0; ni < 4; ni++)
                mma16816(acc[mi][ni], AhF[mi], &BhF[ni >> 1][(ni & 1) * 2]);
        // g2: Wh x Fl
#pragma unroll
        for (int nj = 0; nj < 2; nj++) ldsm4t(BlF[nj], bBl + offBt[nj]);
#pragma unroll
        for (int mi = 0; mi < 2; mi++)
#pragma unroll
            for (int ni = 0; ni < 4; ni++)
                mma16816(acc[mi][ni], AhF[mi], &BlF[ni >> 1][(ni & 1) * 2]);
        // g3: Wl x Fh
#pragma unroll
        for (int mi = 0; mi < 2; mi++) ldsm4(AlF[mi], bAl + offA[mi]);
#pragma unroll
        for (int mi = 0; mi < 2; mi++)
#pragma unroll
            for (int ni = 0; ni < 4; ni++)
                mma16816(acc[mi][ni], AlF[mi], &BhF[ni >> 1][(ni & 1) * 2]);

        CPW(2);
        __syncthreads();
        if (c + 1 < NC) {
            const int nb = (c + 1) & 3;
            const uint32_t bAh = smem_u32(&SA[nb][0][0]);
            const uint32_t bBh = smem_u32(&SBt[nb][0][0]);
#pragma unroll
            for (int mi = 0; mi < 2; mi++) ldsm4(AhF[mi], bAh + offA[mi]);
#pragma unroll
            for (int nj = 0; nj < 2; nj++) ldsm4t(BhF[nj], bBh + offBt[nj]);
        }
    }

    const float beta0 = beta[0];
    const int r0 = mblk * 128 + wm + (lane >> 2);     // channel
    const int c0 = nblk * 64 + wn + 2 * (lane & 3);   // spatial
#pragma unroll
    for (int mi = 0; mi < 2; mi++)
#pragma unroll
        for (int ni = 0; ni < 4; ni++) {
            const float* d = acc[mi][ni];
            const int gr = r0 + 16 * mi, gc = c0 + 8 * ni;
            const size_t o0 = ((size_t)(b * CDIM + gr) * NDIM) + gc;
            const size_t o1 = ((size_t)(b * CDIM + gr + 8) * NDIM) + gc;
            float2 x0 = *(const float2*)(x + o0);
            float2 x1 = *(const float2*)(x + o1);
            *(float2*)(out + o0) = make_float2(fmaf(beta0, d[0], x0.x),
                                               fmaf(beta0, d[1], x0.y));
            *(float2*)(out + o1) = make_float2(fmaf(beta0, d[2], x1.x),
                                               fmaf(beta0, d[3], x1.y));
        }
}

// ===========================================================================
extern "C" void kernel_launch(void* const* d_in, const int* in_sizes, int n_in,
                              void* d_out, int out_size) {
    (void)n_in; (void)out_size;
    const float* x    = (const float*)d_in[0];
    const float* beta = (const float*)d_in[1];
    if (in_sizes[0] == 1) { const float* tmp = x; x = beta; beta = tmp; }
    float* out = (float*)d_out;

    prep_kernel<<<(BDIM * CDIM * NDIM) / (256 * 4), 256>>>(x);
    gram_mma<<<dim3(20, BDIM), 256>>>();
    softmin_kernel<<<dim3(CDIM, BDIM), 128>>>();
    av_mma<<<dim3(NDIM / 64, CDIM / 128, BDIM), 256>>>(x, beta, out);
}

// round 16
// speedup vs baseline: 1.0347x; 1.0347x over previous
#include <cuda_runtime.h>
#include <cuda_bf16.h>
#include <cstdint>

// ===========================================================================
// ChannelAttentionModule (DANet), B=32, C=512, H*W=1024, fp32.
//   S = feat @ feat^T ; W = softmax(rowmax(S)-S) = exp(rowmin-S)/sum ;
//   out = beta * (W @ feat) + x
// R16: revert to the R13 empirical optimum (both failed branches dropped:
// trans-B av [+10us, ALU-bloated codegen] and rotated pipeline [+15us on
// gram]). Riskless micro-deltas only: shuffle-based softmin reductions
// (no __syncthreads), skip duplicate mirror stores on diagonal gram CTAs.
// Both GEMMs: fused 3-term bf16 hi/lo mma.sync, 128x64 tiles, 4-stage
// cp.async pipeline, one barrier per K-chunk.
// ===========================================================================

#define BDIM 32
#define CDIM 512
#define NDIM 1024
#define TSZ   2048                 // shorts per 128x16 A tile
#define BTSZ2 1024                 // shorts per 64x16  B tile

// ---------------- scratch (static device globals: allowed) ----------------
__device__ float          g_scores[(size_t)BDIM * CDIM * CDIM];
__device__ __align__(16) unsigned short g_h [(size_t)BDIM * CDIM * NDIM]; // x hi  [b][c][n]
__device__ __align__(16) unsigned short g_l [(size_t)BDIM * CDIM * NDIM]; // x lo
__device__ __align__(16) unsigned short g_th[(size_t)BDIM * NDIM * CDIM]; // x^T hi [b][n][c]
__device__ __align__(16) unsigned short g_tl[(size_t)BDIM * NDIM * CDIM]; // x^T lo
__device__ __align__(16) unsigned short g_wh[(size_t)BDIM * CDIM * CDIM]; // W hi  [b][c][d]
__device__ __align__(16) unsigned short g_wl[(size_t)BDIM * CDIM * CDIM]; // W lo

// ---------------- helpers ---------------------------------------------------
__device__ __forceinline__ uint32_t smem_u32(const void* p) {
    uint32_t a;
    asm("{ .reg .u64 t; cvta.to.shared.u64 t, %1; cvt.u32.u64 %0, t; }"
        : "=r"(a) : "l"(p));
    return a;
}
__device__ __forceinline__ void ldsm4(uint32_t r[4], uint32_t addr) {
    asm volatile("ldmatrix.sync.aligned.m8n8.x4.shared.b16 {%0,%1,%2,%3}, [%4];"
                 : "=r"(r[0]), "=r"(r[1]), "=r"(r[2]), "=r"(r[3]) : "r"(addr));
}
__device__ __forceinline__ void mma16816(float d[4], const uint32_t a[4],
                                         const uint32_t b[2]) {
    asm volatile(
        "mma.sync.aligned.m16n8k16.row.col.f32.bf16.bf16.f32 "
        "{%0,%1,%2,%3}, {%4,%5,%6,%7}, {%8,%9}, {%0,%1,%2,%3};"
        : "+f"(d[0]), "+f"(d[1]), "+f"(d[2]), "+f"(d[3])
        : "r"(a[0]), "r"(a[1]), "r"(a[2]), "r"(a[3]), "r"(b[0]), "r"(b[1]));
}
__device__ __forceinline__ void cpa(uint32_t s, const void* g) {
    asm volatile("cp.async.cg.shared.global [%0], [%1], 16;" :: "r"(s), "l"(g));
}
#define CPC()  asm volatile("cp.async.commit_group;" ::: "memory")
#define CPW(n) asm volatile("cp.async.wait_group %0;" :: "n"(n) : "memory")

// K-major tile swizzle: row stride 32B, 16B halves swap every 4 rows.
__device__ __forceinline__ uint32_t tswz(int row, int kh) {
    return (uint32_t)(row * 32 + ((kh ^ ((row >> 2) & 1)) << 4));
}

__device__ __forceinline__ void bsplit(float v, unsigned short& h, unsigned short& l) {
    __nv_bfloat16 hh = __float2bfloat16_rn(v);
    float r = v - __bfloat162float(hh);
    __nv_bfloat16 ll = __float2bfloat16_rn(r);
    h = *reinterpret_cast<unsigned short*>(&hh);
    l = *reinterpret_cast<unsigned short*>(&ll);
}

// ===========================================================================
// Shared fused 3-term 128(M) x 64(N) GEMM mainloop, 4-stage pipeline.
// 8 warps as 4M x 2N, warp tile 32x32. Per chunk: 8 ldsm, 24 MMAs,
// ONE __syncthreads. (R13-proven structure — do not rotate; R15 showed the
// rotated variant costs ~15us on gram.)
// ===========================================================================
template <int LD, int NC>
__device__ __forceinline__ void gemm64(
    const unsigned short* __restrict__ Ah, const unsigned short* __restrict__ Al,
    const unsigned short* __restrict__ Bh, const unsigned short* __restrict__ Bl,
    unsigned short (*SA)[2][TSZ],           // [4][2][TSZ]
    unsigned short (*SB)[2][BTSZ2],         // [4][2][BTSZ2]
    float acc[2][4][4])
{
    const int t = threadIdx.x, lane = t & 31, wid = t >> 5;

    const unsigned short* srcA[2] = { Ah, Al };
    const unsigned short* srcB[2] = { Bh, Bl };

    const int crow = t >> 1, ckh = t & 1;                 // A rows 0..127
    const size_t gA = (size_t)crow * LD + ckh * 8;
    const uint32_t sA = tswz(crow, ckh);
    const int bsel = t >> 7;                              // 0: Bh, 1: Bl
    const int bt = t & 127;
    const int brow = bt >> 1, bkh = bt & 1;               // B rows 0..63
    const size_t gB = (size_t)brow * LD + bkh * 8;
    const uint32_t sB = tswz(brow, bkh);

    const int wm = (wid & 3) * 32, wn = (wid >> 2) * 32;
    const int a_r = wm + (lane & 15), a_kh = lane >> 4;
    const int b_r = wn + (lane & 7) + ((lane >> 4) << 3), b_kh = (lane >> 3) & 1;

    uint32_t offA[2], offB[2];
#pragma unroll
    for (int mi = 0; mi < 2; mi++) offA[mi] = tswz(a_r + 16 * mi, a_kh);
#pragma unroll
    for (int nj = 0; nj < 2; nj++) offB[nj] = tswz(b_r + 16 * nj, b_kh);

    // prologue: chunks 0..2
#pragma unroll
    for (int pc = 0; pc < 3; pc++) {
        cpa(smem_u32(&SA[pc][0][0]) + sA, srcA[0] + gA + pc * 16);
        cpa(smem_u32(&SA[pc][1][0]) + sA, srcA[1] + gA + pc * 16);
        cpa(smem_u32(&SB[pc][bsel][0]) + sB, srcB[bsel] + gB + pc * 16);
        CPC();
    }

    for (int c = 0; c < NC; c++) {
        CPW(2);                                  // oldest (chunk c) complete
        __syncthreads();
        if (c + 3 < NC) {
            const int nb = (c + 3) & 3;
            const size_t go = (size_t)(c + 3) * 16;
            cpa(smem_u32(&SA[nb][0][0]) + sA, srcA[0] + gA + go);
            cpa(smem_u32(&SA[nb][1][0]) + sA, srcA[1] + gA + go);
            cpa(smem_u32(&SB[nb][bsel][0]) + sB, srcB[bsel] + gB + go);
        }
        CPC();                                   // may be empty: keeps group count

        const int cb = c & 3;
        const uint32_t bAh = smem_u32(&SA[cb][0][0]);
        const uint32_t bAl = smem_u32(&SA[cb][1][0]);
        const uint32_t bBh = smem_u32(&SB[cb][0][0]);
        const uint32_t bBl = smem_u32(&SB[cb][1][0]);

        uint32_t AhF[2][4], AlF[2][4], BhF[2][4], BlF[2][4];
#pragma unroll
        for (int mi = 0; mi < 2; mi++) ldsm4(AhF[mi], bAh + offA[mi]);
#pragma unroll
        for (int nj = 0; nj < 2; nj++) ldsm4(BhF[nj], bBh + offB[nj]);
#pragma unroll
        for (int mi = 0; mi < 2; mi++)
#pragma unroll
            for (int ni = 0; ni < 4; ni++)
                mma16816(acc[mi][ni], AhF[mi], &BhF[ni >> 1][(ni & 1) * 2]);
#pragma unroll
        for (int nj = 0; nj < 2; nj++) ldsm4(BlF[nj], bBl + offB[nj]);
#pragma unroll
        for (int mi = 0; mi < 2; mi++)
#pragma unroll
            for (int ni = 0; ni < 4; ni++)
                mma16816(acc[mi][ni], AhF[mi], &BlF[ni >> 1][(ni & 1) * 2]);
#pragma unroll
        for (int mi = 0; mi < 2; mi++) ldsm4(AlF[mi], bAl + offA[mi]);
#pragma unroll
        for (int mi = 0; mi < 2; mi++)
#pragma unroll
            for (int ni = 0; ni < 4; ni++)
                mma16816(acc[mi][ni], AlF[mi], &BhF[ni >> 1][(ni & 1) * 2]);
    }
}

// ===========================================================================
// Stage 0: split + transpose:  x -> g_h/g_l ([c][n])  and  g_th/g_tl ([n][c])
// ===========================================================================
__global__ void prep_kernel(const float* __restrict__ x) {
    const int b = blockIdx.z, c0 = blockIdx.y * 32, n0 = blockIdx.x * 32;
    __shared__ float tile[32][33];
    const int t = threadIdx.x;
    const int i = t >> 3, j0 = (t & 7) * 4;

    const size_t src = ((size_t)(b * CDIM + c0 + i) * NDIM) + n0 + j0;
    float4 v = *(const float4*)(x + src);
    tile[i][j0 + 0] = v.x; tile[i][j0 + 1] = v.y;
    tile[i][j0 + 2] = v.z; tile[i][j0 + 3] = v.w;

    unsigned short h[4], l[4];
    bsplit(v.x, h[0], l[0]); bsplit(v.y, h[1], l[1]);
    bsplit(v.z, h[2], l[2]); bsplit(v.w, h[3], l[3]);
    uint2 ph, pl;
    ph.x = h[0] | ((uint32_t)h[1] << 16); ph.y = h[2] | ((uint32_t)h[3] << 16);
    pl.x = l[0] | ((uint32_t)l[1] << 16); pl.y = l[2] | ((uint32_t)l[3] << 16);
    *(uint2*)(g_h + src) = ph;
    *(uint2*)(g_l + src) = pl;

    __syncthreads();

    float f0 = tile[j0 + 0][i], f1 = tile[j0 + 1][i];
    float f2 = tile[j0 + 2][i], f3 = tile[j0 + 3][i];
    bsplit(f0, h[0], l[0]); bsplit(f1, h[1], l[1]);
    bsplit(f2, h[2], l[2]); bsplit(f3, h[3], l[3]);
    ph.x = h[0] | ((uint32_t)h[1] << 16); ph.y = h[2] | ((uint32_t)h[3] << 16);
    pl.x = l[0] | ((uint32_t)l[1] << 16); pl.y = l[2] | ((uint32_t)l[3] << 16);
    const size_t dst = ((size_t)(b * NDIM + n0 + i) * CDIM) + c0 + j0;
    *(uint2*)(g_th + dst) = ph;
    *(uint2*)(g_tl + dst) = pl;
}

// ===========================================================================
// Stage 1: Gram S = F F^T.  128x64 tiles, 20 upper-tri pairs/batch, mirrored.
// ===========================================================================
__global__ __launch_bounds__(256, 2)
void gram_mma() {
    __shared__ unsigned short SA[4][2][TSZ];     // 32 KB (Ah, Al)
    __shared__ unsigned short SB[4][2][BTSZ2];   // 16 KB (Bh, Bl)

    const int b = blockIdx.y;
    int p = blockIdx.x;                          // 0..19
    int ti = 0;
    while (p >= 8 - 2 * ti) { p -= 8 - 2 * ti; ti++; }
    const int tjn = 2 * ti + p;                  // 64-col block, tjn*64 >= ti*128

    float acc[2][4][4];
#pragma unroll
    for (int i = 0; i < 2; i++)
#pragma unroll
        for (int j = 0; j < 4; j++)
#pragma unroll
            for (int k = 0; k < 4; k++) acc[i][j][k] = 0.f;

    gemm64<NDIM, NDIM / 16>(
        g_h + (size_t)(b * CDIM + ti * 128) * NDIM,
        g_l + (size_t)(b * CDIM + ti * 128) * NDIM,
        g_h + (size_t)(b * CDIM + tjn * 64) * NDIM,
        g_l + (size_t)(b * CDIM + tjn * 64) * NDIM,
        SA, SB, acc);

    const int lane = threadIdx.x & 31, wid = threadIdx.x >> 5;
    const int wm = (wid & 3) * 32, wn = (wid >> 2) * 32;
    float* Cb = g_scores + (size_t)b * CDIM * CDIM;
    const int r0 = ti * 128 + wm + (lane >> 2);
    const int c0 = tjn * 64 + wn + 2 * (lane & 3);
    // diagonal-band CTAs (tjn in {2ti, 2ti+1}) overlap the mirror with the
    // direct store region; skip redundant mirror writes there when the
    // column block lies fully inside this CTA's row range.
    const bool band = (tjn >> 1) == ti;
#pragma unroll
    for (int mi = 0; mi < 2; mi++)
#pragma unroll
        for (int ni = 0; ni < 4; ni++) {
            const float* d = acc[mi][ni];
            const int gr = r0 + 16 * mi, gc = c0 + 8 * ni;
            *(float2*)&Cb[(size_t)gr * CDIM + gc]       = make_float2(d[0], d[1]);
            *(float2*)&Cb[(size_t)(gr + 8) * CDIM + gc] = make_float2(d[2], d[3]);
            if (!band) {
                Cb[(size_t)gc * CDIM + gr]           = d[0];
                Cb[(size_t)(gc + 1) * CDIM + gr]     = d[1];
                Cb[(size_t)gc * CDIM + gr + 8]       = d[2];
                Cb[(size_t)(gc + 1) * CDIM + gr + 8] = d[3];
            }
        }
    if (band) {
        // mirror only the strictly-lower part of the band block (the part
        // not covered by some CTA's direct store): rows gc of S map under
        // this CTA's own direct region, so mirror writes ARE the direct
        // values of the transposed coordinates — write them (they fall in
        // this tile's row range covered above only when gc in [ti*128,
        // ti*128+128) AND gr in [tjn*64, tjn*64+64); everything else needs
        // the mirror).
#pragma unroll
        for (int mi = 0; mi < 2; mi++)
#pragma unroll
            for (int ni = 0; ni < 4; ni++) {
                const float* d = acc[mi][ni];
                const int gr = r0 + 16 * mi, gc = c0 + 8 * ni;
                const bool covered0 = (gr >= tjn * 64) && (gr < tjn * 64 + 64);
                if (!covered0) {
                    Cb[(size_t)gc * CDIM + gr]           = d[0];
                    Cb[(size_t)(gc + 1) * CDIM + gr]     = d[1];
                }
                const bool covered1 = (gr + 8 >= tjn * 64) && (gr + 8 < tjn * 64 + 64);
                if (!covered1) {
                    Cb[(size_t)gc * CDIM + gr + 8]       = d[2];
                    Cb[(size_t)(gc + 1) * CDIM + gr + 8] = d[3];
                }
            }
    }
}

// ===========================================================================
// Stage 2: softmin rows of S -> bf16 hi/lo weights. Pure-shuffle reductions
// within warps + single smem exchange (no second __syncthreads round-trip).
// ===========================================================================
__global__ void softmin_kernel() {
    const int b = blockIdx.y, r = blockIdx.x;
    const float* row = g_scores + ((size_t)b * CDIM + r) * CDIM;
    const int t = threadIdx.x;
    const int warp = t >> 5, lane = t & 31;

    float4 v = ((const float4*)row)[t];
    float mn = fminf(fminf(v.x, v.y), fminf(v.z, v.w));
#pragma unroll
    for (int o = 16; o > 0; o >>= 1)
        mn = fminf(mn, __shfl_xor_sync(0xffffffffu, mn, o));

    __shared__ float rmin[4], rsum[4];
    if (lane == 0) rmin[warp] = mn;
    __syncthreads();
    mn = fminf(fminf(rmin[0], rmin[1]), fminf(rmin[2], rmin[3]));

    float4 e;
    e.x = __expf(mn - v.x); e.y = __expf(mn - v.y);
    e.z = __expf(mn - v.z); e.w = __expf(mn - v.w);
    float s = e.x + e.y + e.z + e.w;
#pragma unroll
    for (int o = 16; o > 0; o >>= 1)
        s += __shfl_xor_sync(0xffffffffu, s, o);
    if (lane == 0) rsum[warp] = s;
    __syncthreads();
    s = rsum[0] + rsum[1] + rsum[2] + rsum[3];

    const float inv = __frcp_rn(s);
    unsigned short h[4], l[4];
    bsplit(e.x * inv, h[0], l[0]); bsplit(e.y * inv, h[1], l[1]);
    bsplit(e.z * inv, h[2], l[2]); bsplit(e.w * inv, h[3], l[3]);
    uint2 ph, pl;
    ph.x = h[0] | ((uint32_t)h[1] << 16); ph.y = h[2] | ((uint32_t)h[3] << 16);
    pl.x = l[0] | ((uint32_t)l[1] << 16); pl.y = l[2] | ((uint32_t)l[3] << 16);
    const size_t off = ((size_t)b * CDIM + r) * CDIM + t * 4;
    *(uint2*)(g_wh + off) = ph;
    *(uint2*)(g_wl + off) = pl;
}

// ===========================================================================
// Stage 3: out = beta * (W @ feat) + x.  128x64 tiles, 4-stage, 2048 CTAs.
// A = W [c][d] hi/lo (LD=CDIM), B = feat^T [n][c] hi/lo (LD=CDIM), NC=32.
// ===========================================================================
__global__ __launch_bounds__(256, 2)
void av_mma(const float* __restrict__ x, const float* __restrict__ beta,
            float* __restrict__ out) {
    __shared__ unsigned short SA[4][2][TSZ];     // 32 KB (Wh, Wl)
    __shared__ unsigned short SB[4][2][BTSZ2];   // 16 KB (Fh, Fl)

    const int b = blockIdx.z, nblk = blockIdx.x, mblk = blockIdx.y;

    float acc[2][4][4];
#pragma unroll
    for (int i = 0; i < 2; i++)
#pragma unroll
        for (int j = 0; j < 4; j++)
#pragma unroll
            for (int k = 0; k < 4; k++) acc[i][j][k] = 0.f;

    gemm64<CDIM, CDIM / 16>(
        g_wh + (size_t)(b * CDIM + mblk * 128) * CDIM,
        g_wl + (size_t)(b * CDIM + mblk * 128) * CDIM,
        g_th + (size_t)(b * NDIM + nblk * 64) * CDIM,
        g_tl + (size_t)(b * NDIM + nblk * 64) * CDIM,
        SA, SB, acc);

    const int lane = threadIdx.x & 31, wid = threadIdx.x >> 5;
    const int wm = (wid & 3) * 32, wn = (wid >> 2) * 32;
    const float beta0 = beta[0];
    const int r0 = mblk * 128 + wm + (lane >> 2);     // channel
    const int c0 = nblk * 64 + wn + 2 * (lane & 3);   // spatial
#pragma unroll
    for (int mi = 0; mi < 2; mi++)
#pragma unroll
        for (int ni = 0; ni < 4; ni++) {
            const float* d = acc[mi][ni];
            const int gr = r0 + 16 * mi, gc = c0 + 8 * ni;
            const size_t o0 = ((size_t)(b * CDIM + gr) * NDIM) + gc;
            const size_t o1 = ((size_t)(b * CDIM + gr + 8) * NDIM) + gc;
            float2 x0 = *(const float2*)(x + o0);
            float2 x1 = *(const float2*)(x + o1);
            *(float2*)(out + o0) = make_float2(fmaf(beta0, d[0], x0.x),
                                               fmaf(beta0, d[1], x0.y));
            *(float2*)(out + o1) = make_float2(fmaf(beta0, d[2], x1.x),
                                               fmaf(beta0, d[3], x1.y));
        }
}

// ===========================================================================
extern "C" void kernel_launch(void* const* d_in, const int* in_sizes, int n_in,
                              void* d_out, int out_size) {
    (void)n_in; (void)out_size;
    const float* x    = (const float*)d_in[0];
    const float* beta = (const float*)d_in[1];
    if (in_sizes[0] == 1) { const float* tmp = x; x = beta; beta = tmp; }
    float* out = (float*)d_out;

    prep_kernel<<<dim3(NDIM / 32, CDIM / 32, BDIM), 256>>>(x);
    gram_mma<<<dim3(20, BDIM), 256>>>();
    softmin_kernel<<<dim3(CDIM, BDIM), 128>>>();
    av_mma<<<dim3(NDIM / 64, CDIM / 128, BDIM), 256>>>(x, beta, out);
}